// round 8
// baseline (speedup 1.0000x reference)
#include <cuda_runtime.h>

#define KPTS    16384
#define NATOMS  1024
#define NB      16
#define NSRC    17      // source 0 = C, sources 1..16 = C1[b]
#define NC      5       // cells per axis (h = 2.0)
#define NCELLS  125
#define NSLICE  16      // dom binning slices (1024 points each)
#define SLCAP   40      // dom points per (cell, slice) capacity (mean 8.2)
#define ACAP    40      // atoms per (source, cell) capacity (mean 8.2)
#define DCAP    640     // max dom points per cell (16*40)
#define SCAP    448     // gathered neighbor-atom capacity (mean 221)
#define NPAIR   (SCAP / 2)

// L = inv2s * log2(e) = 2*pi * 1.4426950408889634
#define LCONST  9.064720283654388f
#define INV2L   (1.0f / (2.0f * LCONST))

typedef unsigned long long u64;

// static scratch (no allocations allowed)
__device__ float4 g_binned[NSRC * NCELLS * ACAP];
__device__ int    g_acount[NSRC * NCELLS];
__device__ int    g_dslice[NCELLS * NSLICE * SLCAP];
__device__ int    g_dcnt2[NCELLS * NSLICE];
__device__ float4 g_kcoef[KPTS];
__device__ float  g_theta[NSRC * KPTS];

__device__ __forceinline__ int cell_of(float x, float y, float z) {
    int cx = min(NC - 1, max(0, (int)(x * 0.5f)));
    int cy = min(NC - 1, max(0, (int)(y * 0.5f)));
    int cz = min(NC - 1, max(0, (int)(z * 0.5f)));
    return (cz * NC + cy) * NC + cx;
}

// ---- packed f32x2 helpers --------------------------------------------------
__device__ __forceinline__ u64 pk2(float lo, float hi) {
    u64 r; asm("mov.b64 %0, {%1, %2};" : "=l"(r) : "f"(lo), "f"(hi)); return r;
}
__device__ __forceinline__ void upk2(u64 v, float& lo, float& hi) {
    asm("mov.b64 {%0, %1}, %2;" : "=f"(lo), "=f"(hi) : "l"(v));
}
__device__ __forceinline__ u64 fma2(u64 a, u64 b, u64 c) {
    u64 r; asm("fma.rn.f32x2 %0, %1, %2, %3;" : "=l"(r) : "l"(a), "l"(b), "l"(c)); return r;
}
__device__ __forceinline__ u64 add2(u64 a, u64 b) {
    u64 r; asm("add.rn.f32x2 %0, %1, %2;" : "=l"(r) : "l"(a), "l"(b)); return r;
}
__device__ __forceinline__ float ex2(float a) {
    float e; asm("ex2.approx.ftz.f32 %0, %1;" : "=f"(e) : "f"(a)); return e;
}

// ---------------------------------------------------------------------------
// Single prep launch, 33 blocks x 1024 threads.
// Blocks 0..15: dom binning, one 1024-point slice per block (one point per
//   thread). Private smem histogram -> per-(cell,slice) segment. Scattered
//   stores are spread across 16 SMs' L1s instead of one. Slot order within a
//   slice comes from smem atomics: FP-IRRELEVANT (each point's theta is
//   written to its own index; the final dot is summed in fixed k order).
// Blocks 16..32: deterministic atom binning for source s = blockIdx.x-16
//   (thread = atom, match_any rank + parallel across-warp prefix; atom index
//   order preserved -> fixed theta summation order).
// ---------------------------------------------------------------------------
__global__ void __launch_bounds__(1024) prep_kernel(const float* __restrict__ C1,
                                                    const float* __restrict__ C,
                                                    const float* __restrict__ dom) {
    const int tid = threadIdx.x;
    const int bid = blockIdx.x;

    if (bid < NSLICE) {
        __shared__ int hist[NCELLS];
        if (tid < NCELLS) hist[tid] = 0;
        const int k = bid * 1024 + tid;
        const float x = dom[k * 3 + 0];
        const float y = dom[k * 3 + 1];
        const float z = dom[k * 3 + 2];
        g_kcoef[k] = make_float4(x, y, z, -LCONST * (x * x + y * y + z * z));
        const int c = cell_of(x, y, z);
        __syncthreads();
        int slot = atomicAdd(&hist[c], 1);
        if (slot < SLCAP) g_dslice[(c * NSLICE + bid) * SLCAP + slot] = k;
        __syncthreads();
        if (tid < NCELLS) g_dcnt2[tid * NSLICE + bid] = min(hist[tid], SLCAP);
    } else {
        __shared__ int wcnt[32 * 128];           // [warp][cell]
        const int s = bid - NSLICE;
        const float* src = (s == 0) ? C : (C1 + (size_t)(s - 1) * NATOMS * 3);
        const int lane = tid & 31;
        const int w    = tid >> 5;

        #pragma unroll
        for (int i = 0; i < 4; ++i) wcnt[tid + i * 1024] = 0;

        const float x = src[tid * 3 + 0];
        const float y = src[tid * 3 + 1];
        const float z = src[tid * 3 + 2];
        const int   c = cell_of(x, y, z);
        __syncthreads();

        unsigned mm  = __match_any_sync(0xffffffffu, c);
        int     rank = __popc(mm & ((1u << lane) - 1u));
        if (rank == 0) wcnt[w * 128 + c] = __popc(mm);
        __syncthreads();

        if (tid < NCELLS) {
            int acc = 0;
            #pragma unroll
            for (int ww = 0; ww < 32; ++ww) {
                int v = wcnt[ww * 128 + tid];
                wcnt[ww * 128 + tid] = acc;       // exclusive warp base
                acc += v;
            }
            g_acount[s * NCELLS + tid] = min(acc, ACAP);
        }
        __syncthreads();

        int pos = wcnt[w * 128 + c] + rank;
        if (pos < ACAP) {
            float phi = x * x + y * y + z * z;
            g_binned[(s * NCELLS + c) * ACAP + pos] =
                make_float4(2.f * LCONST * x, 2.f * LCONST * y,
                            2.f * LCONST * z, -LCONST * phi);
        }
    }
}

// ---------------------------------------------------------------------------
// theta[s][k] = sum over pruned neighbor atoms of exp2(ax*kx+ay*ky+az*kz+aw+kw).
// Gather 27-cell atoms, then prune to atoms within distance 2.0 of the home
// cell CUBE (dropped atoms contribute < 2^-36 to any point in the cell).
// Atoms processed in packed pairs via fma.rn.f32x2; odd count padded with a
// dummy (aw = -1e30 -> exp2 flushes to 0 under ftz). Deterministic order.
// ---------------------------------------------------------------------------
__global__ void __launch_bounds__(160) theta_kernel() {
    __shared__ float4     satoms[SCAP];
    __shared__ ulonglong2 sA[NPAIR];    // (x0,x1),(y0,y1)
    __shared__ ulonglong2 sB[NPAIR];    // (z0,z1),(w0,w1)
    __shared__ int        ncl[27], scnt[27];
    __shared__ int        scnt16[NSLICE], soff16[NSLICE + 1];
    __shared__ int        sdlist[DCAP];
    __shared__ int        sNkeep;
    const int cell = blockIdx.x;
    const int s    = blockIdx.y;
    const int tid  = threadIdx.x;
    const int lane = tid & 31;
    const int cx = cell % NC, cy = (cell / NC) % NC, cz = cell / (NC * NC);

    // neighbor cell ids + counts, and home-cell dom segment counts (parallel)
    if (tid < 27) {
        int dx = tid % 3 - 1, dy = (tid / 3) % 3 - 1, dz = tid / 9 - 1;
        int nx = cx + dx, ny = cy + dy, nz = cz + dz;
        bool ok = (unsigned)nx < NC && (unsigned)ny < NC && (unsigned)nz < NC;
        int nc2 = ok ? (nz * NC + ny) * NC + nx : -1;
        ncl[tid]  = nc2;
        scnt[tid] = ok ? g_acount[s * NCELLS + nc2] : 0;
    }
    if (tid >= 32 && tid < 32 + NSLICE)
        scnt16[tid - 32] = g_dcnt2[cell * NSLICE + (tid - 32)];
    __syncthreads();
    if (tid == 0) {
        int a = 0;
        #pragma unroll
        for (int i = 0; i < NSLICE; ++i) { soff16[i] = a; a += scnt16[i]; }
        soff16[NSLICE] = a;
    }
    __syncthreads();

    // stitch dom segments into one contiguous smem list
    for (int idx = tid; idx < NSLICE * SLCAP; idx += 160) {
        int sl = idx / SLCAP, j = idx % SLCAP;
        if (j < scnt16[sl])
            sdlist[soff16[sl] + j] = g_dslice[(cell * NSLICE + sl) * SLCAP + j];
    }

    // gather neighbor atoms (uniform traversal)
    int base = 0;
    #pragma unroll 1
    for (int ci = 0; ci < 27; ++ci) {
        int cnt = scnt[ci];
        if (cnt) {
            const float4* srcp = g_binned + (s * NCELLS + ncl[ci]) * ACAP;
            for (int i = tid; i < cnt; i += 160) {
                int pos = base + i;
                if (pos < SCAP) satoms[pos] = srcp[i];
            }
            base += cnt;
        }
    }
    const int ntot = min(base, SCAP);
    __syncthreads();

    // prune: keep atoms within distance 2.0 of the home cell cube.
    // in-place warp-0 ballot compaction (deterministic, index order kept).
    if (tid < 32) {
        const float lox = cx * 2.f, hix = lox + 2.f;
        const float loy = cy * 2.f, hiy = loy + 2.f;
        const float loz = cz * 2.f, hiz = loz + 2.f;
        int nk = 0;
        for (int i0 = 0; i0 < ntot; i0 += 32) {
            int i = i0 + lane;
            bool keep = false;
            float4 a;
            if (i < ntot) {
                a = satoms[i];
                float x = a.x * INV2L, y = a.y * INV2L, z = a.z * INV2L;
                float dx = fmaxf(fmaxf(lox - x, x - hix), 0.f);
                float dy = fmaxf(fmaxf(loy - y, y - hiy), 0.f);
                float dz = fmaxf(fmaxf(loz - z, z - hiz), 0.f);
                keep = fmaf(dx, dx, fmaf(dy, dy, dz * dz)) <= 4.0f;
            }
            unsigned m = __ballot_sync(0xffffffffu, keep);
            __syncwarp();
            if (keep) satoms[nk + __popc(m & ((1u << lane) - 1u))] = a;
            nk += __popc(m);
        }
        if (lane == 0) {
            if (nk & 1) { satoms[nk] = make_float4(0.f, 0.f, 0.f, -1e30f); }
            sNkeep = nk;
        }
    }
    __syncthreads();

    const int total  = sNkeep;
    const int npairs = (total + 1) >> 1;

    // pack atom pairs for f32x2 consumption
    for (int jp = tid; jp < npairs; jp += 160) {
        float4 a = satoms[2 * jp];
        float4 b = satoms[2 * jp + 1];
        sA[jp] = make_ulonglong2(pk2(a.x, b.x), pk2(a.y, b.y));
        sB[jp] = make_ulonglong2(pk2(a.z, b.z), pk2(a.w, b.w));
    }
    __syncthreads();

    const int npts = soff16[NSLICE];
    for (int p = tid; p < npts; p += 160) {
        const int idx = sdlist[p];
        const float4 kc = g_kcoef[idx];
        const u64 kx2 = pk2(kc.x, kc.x);
        const u64 ky2 = pk2(kc.y, kc.y);
        const u64 kz2 = pk2(kc.z, kc.z);
        const u64 kw2 = pk2(kc.w, kc.w);
        u64 acc = 0ull;                       // (0.f, 0.f)
        #pragma unroll 4
        for (int jp = 0; jp < npairs; ++jp) {
            ulonglong2 A = sA[jp];
            ulonglong2 B = sB[jp];
            u64 t = add2(B.y, kw2);
            t = fma2(kz2, B.x, t);
            t = fma2(ky2, A.y, t);
            t = fma2(kx2, A.x, t);
            float lo, hi; upk2(t, lo, hi);
            acc = add2(acc, pk2(ex2(lo), ex2(hi)));
        }
        float a0, a1; upk2(acc, a0, a1);
        g_theta[s * KPTS + idx] = a0 + a1;
    }
}

// ---------------------------------------------------------------------------
// out[b] = 1 - clip( scale * sum_k theta[b+1][k]*theta[0][k], 0, 1 )
// scale = A*V/sqrt(n1*n2) = 8 * (1000/16384) / 1024
// ---------------------------------------------------------------------------
__global__ void reduce_kernel(float* __restrict__ out) {
    __shared__ float red[256];
    const int b = blockIdx.x;
    const float* tb = g_theta + (size_t)(1 + b) * KPTS;
    const float* t0 = g_theta;
    float p = 0.f;
    for (int k = threadIdx.x; k < KPTS; k += 256)
        p += tb[k] * t0[k];
    red[threadIdx.x] = p;
    __syncthreads();
    for (int st = 128; st > 0; st >>= 1) {
        if (threadIdx.x < st) red[threadIdx.x] += red[threadIdx.x + st];
        __syncthreads();
    }
    if (threadIdx.x == 0) {
        float dot = 4.76837158203125e-4f * red[0];
        dot = fminf(fmaxf(dot, 0.f), 1.f);
        out[b] = 1.f - dot;
    }
}

extern "C" void kernel_launch(void* const* d_in, const int* in_sizes, int n_in,
                              void* d_out, int out_size) {
    const float* C1  = (const float*)d_in[0];   // (16, 1024, 3)
    const float* C   = (const float*)d_in[1];   // (1024, 3)
    const float* dom = (const float*)d_in[2];   // (16384, 3)

    prep_kernel<<<NSLICE + NSRC, 1024>>>(C1, C, dom);
    theta_kernel<<<dim3(NCELLS, NSRC), 160>>>();
    reduce_kernel<<<NB, 256>>>((float*)d_out);
}

// round 9
// speedup vs baseline: 1.5445x; 1.5445x over previous
#include <cuda_runtime.h>

#define KPTS    16384
#define NATOMS  1024
#define NB      16
#define NSRC    17      // source 0 = C, sources 1..16 = C1[b]
#define NC      5       // cells per axis (h = 2.0)
#define NCELLS  125
#define NSLICE  16      // dom binning slices (1024 points each)
#define SLCAP   40      // dom points per (cell, slice) capacity (mean 8.2)
#define ACAP    40      // atoms per (source, cell) capacity (mean 8.2)
#define DCAP    640     // max dom points per cell (16*40)
#define SCAP    448     // gathered neighbor-atom capacity (mean 221)
#define NPAIR   (SCAP / 2)

// L = inv2s * log2(e) = 2*pi * 1.4426950408889634
#define LCONST  9.064720283654388f
#define INV2L   (1.0f / (2.0f * LCONST))

typedef unsigned long long u64;

// static scratch (no allocations allowed)
__device__ float4     g_binned[NSRC * NCELLS * ACAP];
__device__ int        g_acount[NSRC * NCELLS];
__device__ int        g_dslice[NCELLS * NSLICE * SLCAP];
__device__ int        g_dcnt2[NCELLS * NSLICE];
__device__ float4     g_kcoef[KPTS];
__device__ ulonglong2 g_pairsA[NSRC * NCELLS * NPAIR];  // (x0,x1),(y0,y1)
__device__ ulonglong2 g_pairsB[NSRC * NCELLS * NPAIR];  // (z0,z1),(w0,w1)
__device__ int        g_pcount[NSRC * NCELLS];          // pair counts
__device__ int        g_kidx[NCELLS * DCAP];            // stitched point ids
__device__ float4     g_kc[NCELLS * DCAP];              // stitched kcoefs
__device__ int        g_dcountc[NCELLS];
__device__ float      g_theta[NSRC * KPTS];

__device__ __forceinline__ int cell_of(float x, float y, float z) {
    int cx = min(NC - 1, max(0, (int)(x * 0.5f)));
    int cy = min(NC - 1, max(0, (int)(y * 0.5f)));
    int cz = min(NC - 1, max(0, (int)(z * 0.5f)));
    return (cz * NC + cy) * NC + cx;
}

// ---- packed f32x2 helpers --------------------------------------------------
__device__ __forceinline__ u64 pk2(float lo, float hi) {
    u64 r; asm("mov.b64 %0, {%1, %2};" : "=l"(r) : "f"(lo), "f"(hi)); return r;
}
__device__ __forceinline__ void upk2(u64 v, float& lo, float& hi) {
    asm("mov.b64 {%0, %1}, %2;" : "=f"(lo), "=f"(hi) : "l"(v));
}
__device__ __forceinline__ u64 fma2(u64 a, u64 b, u64 c) {
    u64 r; asm("fma.rn.f32x2 %0, %1, %2, %3;" : "=l"(r) : "l"(a), "l"(b), "l"(c)); return r;
}
__device__ __forceinline__ u64 add2(u64 a, u64 b) {
    u64 r; asm("add.rn.f32x2 %0, %1, %2;" : "=l"(r) : "l"(a), "l"(b)); return r;
}
__device__ __forceinline__ float ex2(float a) {
    float e; asm("ex2.approx.ftz.f32 %0, %1;" : "=f"(e) : "f"(a)); return e;
}

// ---------------------------------------------------------------------------
// prep1: 33 blocks x 1024 threads.
// Blocks 0..15: dom binning by 1024-point slice (slot order from smem atomics
//   is FP-irrelevant: each point's theta goes to its own index and the final
//   dot is summed in fixed k order). Also writes per-point kcoef.
// Blocks 16..32: deterministic atom binning (atom index order preserved).
// ---------------------------------------------------------------------------
__global__ void __launch_bounds__(1024) prep1_kernel(const float* __restrict__ C1,
                                                     const float* __restrict__ C,
                                                     const float* __restrict__ dom) {
    const int tid = threadIdx.x;
    const int bid = blockIdx.x;

    if (bid < NSLICE) {
        __shared__ int hist[NCELLS];
        if (tid < NCELLS) hist[tid] = 0;
        const int k = bid * 1024 + tid;
        const float x = dom[k * 3 + 0];
        const float y = dom[k * 3 + 1];
        const float z = dom[k * 3 + 2];
        g_kcoef[k] = make_float4(x, y, z, -LCONST * (x * x + y * y + z * z));
        const int c = cell_of(x, y, z);
        __syncthreads();
        int slot = atomicAdd(&hist[c], 1);
        if (slot < SLCAP) g_dslice[(c * NSLICE + bid) * SLCAP + slot] = k;
        __syncthreads();
        if (tid < NCELLS) g_dcnt2[tid * NSLICE + bid] = min(hist[tid], SLCAP);
    } else {
        __shared__ int wcnt[32 * 128];           // [warp][cell]
        const int s = bid - NSLICE;
        const float* src = (s == 0) ? C : (C1 + (size_t)(s - 1) * NATOMS * 3);
        const int lane = tid & 31;
        const int w    = tid >> 5;

        #pragma unroll
        for (int i = 0; i < 4; ++i) wcnt[tid + i * 1024] = 0;

        const float x = src[tid * 3 + 0];
        const float y = src[tid * 3 + 1];
        const float z = src[tid * 3 + 2];
        const int   c = cell_of(x, y, z);
        __syncthreads();

        unsigned mm  = __match_any_sync(0xffffffffu, c);
        int     rank = __popc(mm & ((1u << lane) - 1u));
        if (rank == 0) wcnt[w * 128 + c] = __popc(mm);
        __syncthreads();

        if (tid < NCELLS) {
            int acc = 0;
            #pragma unroll
            for (int ww = 0; ww < 32; ++ww) {
                int v = wcnt[ww * 128 + tid];
                wcnt[ww * 128 + tid] = acc;       // exclusive warp base
                acc += v;
            }
            g_acount[s * NCELLS + tid] = min(acc, ACAP);
        }
        __syncthreads();

        int pos = wcnt[w * 128 + c] + rank;
        if (pos < ACAP) {
            float phi = x * x + y * y + z * z;
            g_binned[(s * NCELLS + c) * ACAP + pos] =
                make_float4(2.f * LCONST * x, 2.f * LCONST * y,
                            2.f * LCONST * z, -LCONST * phi);
        }
    }
}

// ---------------------------------------------------------------------------
// prep2: grid (125, 17) x 128 threads. Per (cell, source):
//   gather 27-cell neighbor atoms (deterministic order), prune to atoms
//   within distance 2.0 of the home cell cube (dropped terms < 2^-36 each),
//   pack into f32x2 pairs, write to global pair lists.
// Blocks with s==0 additionally stitch the cell's dom points into contiguous
//   (idx, kcoef) arrays so theta reads them with zero preamble.
// ---------------------------------------------------------------------------
__global__ void __launch_bounds__(128) prep2_kernel() {
    __shared__ float4 satoms[SCAP + 1];
    __shared__ int    ncl[27], scnt[27];
    __shared__ int    sNk;
    const int cell = blockIdx.x;
    const int s    = blockIdx.y;
    const int tid  = threadIdx.x;
    const int lane = tid & 31;
    const int cx = cell % NC, cy = (cell / NC) % NC, cz = cell / (NC * NC);

    if (tid < 27) {
        int dx = tid % 3 - 1, dy = (tid / 3) % 3 - 1, dz = tid / 9 - 1;
        int nx = cx + dx, ny = cy + dy, nz = cz + dz;
        bool ok = (unsigned)nx < NC && (unsigned)ny < NC && (unsigned)nz < NC;
        int nc2 = ok ? (nz * NC + ny) * NC + nx : -1;
        ncl[tid]  = nc2;
        scnt[tid] = ok ? g_acount[s * NCELLS + nc2] : 0;
    }
    __syncthreads();

    // gather (uniform traversal, deterministic order)
    int base = 0;
    #pragma unroll 1
    for (int ci = 0; ci < 27; ++ci) {
        int cnt = scnt[ci];
        if (cnt) {
            const float4* srcp = g_binned + (s * NCELLS + ncl[ci]) * ACAP;
            for (int i = tid; i < cnt; i += 128) {
                int pos = base + i;
                if (pos < SCAP) satoms[pos] = srcp[i];
            }
            base += cnt;
        }
    }
    const int ntot = min(base, SCAP);
    __syncthreads();

    // prune (warp 0, deterministic in-place ballot compaction)
    if (tid < 32) {
        const float lox = cx * 2.f, hix = lox + 2.f;
        const float loy = cy * 2.f, hiy = loy + 2.f;
        const float loz = cz * 2.f, hiz = loz + 2.f;
        int nk = 0;
        for (int i0 = 0; i0 < ntot; i0 += 32) {
            int i = i0 + lane;
            bool keep = false;
            float4 a;
            if (i < ntot) {
                a = satoms[i];
                float x = a.x * INV2L, y = a.y * INV2L, z = a.z * INV2L;
                float dx = fmaxf(fmaxf(lox - x, x - hix), 0.f);
                float dy = fmaxf(fmaxf(loy - y, y - hiy), 0.f);
                float dz = fmaxf(fmaxf(loz - z, z - hiz), 0.f);
                keep = fmaf(dx, dx, fmaf(dy, dy, dz * dz)) <= 4.0f;
            }
            unsigned m = __ballot_sync(0xffffffffu, keep);
            __syncwarp();
            if (keep) satoms[nk + __popc(m & ((1u << lane) - 1u))] = a;
            nk += __popc(m);
        }
        if (lane == 0) {
            if (nk & 1) satoms[nk] = make_float4(0.f, 0.f, 0.f, -1e30f);
            sNk = nk;
        }
    }
    __syncthreads();

    const int npairs = (sNk + 1) >> 1;
    ulonglong2* gA = g_pairsA + (size_t)(s * NCELLS + cell) * NPAIR;
    ulonglong2* gB = g_pairsB + (size_t)(s * NCELLS + cell) * NPAIR;
    for (int jp = tid; jp < npairs; jp += 128) {
        float4 a = satoms[2 * jp];
        float4 b = satoms[2 * jp + 1];
        gA[jp] = make_ulonglong2(pk2(a.x, b.x), pk2(a.y, b.y));
        gB[jp] = make_ulonglong2(pk2(a.z, b.z), pk2(a.w, b.w));
    }
    if (tid == 0) g_pcount[s * NCELLS + cell] = npairs;

    if (s == 0) {
        // stitch this cell's dom points into contiguous (idx, kcoef) arrays
        __shared__ int scnt16[NSLICE], soff16[NSLICE + 1];
        if (tid < NSLICE) scnt16[tid] = g_dcnt2[cell * NSLICE + tid];
        __syncthreads();
        if (tid == 0) {
            int a = 0;
            #pragma unroll
            for (int i = 0; i < NSLICE; ++i) { soff16[i] = a; a += scnt16[i]; }
            soff16[NSLICE] = a;
            g_dcountc[cell] = a;
        }
        __syncthreads();
        for (int idx = tid; idx < NSLICE * SLCAP; idx += 128) {
            int sl = idx / SLCAP, j = idx % SLCAP;
            if (j < scnt16[sl]) {
                int k = g_dslice[(cell * NSLICE + sl) * SLCAP + j];
                int pos = soff16[sl] + j;
                g_kidx[cell * DCAP + pos] = k;
                g_kc[cell * DCAP + pos]   = g_kcoef[k];
            }
        }
    }
}

// ---------------------------------------------------------------------------
// theta: grid (125, 17) x 160 threads, smem = pair buffer only (~7.2 KB).
// Preamble is a strided copy of the packed pair list + one sync; inner loop
// is the MUFU-bound f32x2 chain. Deterministic summation order.
// ---------------------------------------------------------------------------
__global__ void __launch_bounds__(160) theta_kernel() {
    __shared__ ulonglong2 sA[NPAIR];
    __shared__ ulonglong2 sB[NPAIR];
    const int cell = blockIdx.x;
    const int s    = blockIdx.y;
    const int tid  = threadIdx.x;

    const int npairs = g_pcount[s * NCELLS + cell];
    const int npts   = g_dcountc[cell];
    const ulonglong2* gA = g_pairsA + (size_t)(s * NCELLS + cell) * NPAIR;
    const ulonglong2* gB = g_pairsB + (size_t)(s * NCELLS + cell) * NPAIR;
    for (int i = tid; i < npairs; i += 160) {
        sA[i] = gA[i];
        sB[i] = gB[i];
    }
    __syncthreads();

    for (int p = tid; p < npts; p += 160) {
        const int idx = g_kidx[cell * DCAP + p];
        const float4 kc = g_kc[cell * DCAP + p];
        const u64 kx2 = pk2(kc.x, kc.x);
        const u64 ky2 = pk2(kc.y, kc.y);
        const u64 kz2 = pk2(kc.z, kc.z);
        const u64 kw2 = pk2(kc.w, kc.w);
        u64 acc = 0ull;
        #pragma unroll 4
        for (int jp = 0; jp < npairs; ++jp) {
            ulonglong2 A = sA[jp];
            ulonglong2 B = sB[jp];
            u64 t = add2(B.y, kw2);
            t = fma2(kz2, B.x, t);
            t = fma2(ky2, A.y, t);
            t = fma2(kx2, A.x, t);
            float lo, hi; upk2(t, lo, hi);
            acc = add2(acc, pk2(ex2(lo), ex2(hi)));
        }
        float a0, a1; upk2(acc, a0, a1);
        g_theta[s * KPTS + idx] = a0 + a1;
    }
}

// ---------------------------------------------------------------------------
// out[b] = 1 - clip( scale * sum_k theta[b+1][k]*theta[0][k], 0, 1 )
// scale = A*V/sqrt(n1*n2) = 8 * (1000/16384) / 1024
// ---------------------------------------------------------------------------
__global__ void reduce_kernel(float* __restrict__ out) {
    __shared__ float red[256];
    const int b = blockIdx.x;
    const float* tb = g_theta + (size_t)(1 + b) * KPTS;
    const float* t0 = g_theta;
    float p = 0.f;
    for (int k = threadIdx.x; k < KPTS; k += 256)
        p += tb[k] * t0[k];
    red[threadIdx.x] = p;
    __syncthreads();
    for (int st = 128; st > 0; st >>= 1) {
        if (threadIdx.x < st) red[threadIdx.x] += red[threadIdx.x + st];
        __syncthreads();
    }
    if (threadIdx.x == 0) {
        float dot = 4.76837158203125e-4f * red[0];
        dot = fminf(fmaxf(dot, 0.f), 1.f);
        out[b] = 1.f - dot;
    }
}

extern "C" void kernel_launch(void* const* d_in, const int* in_sizes, int n_in,
                              void* d_out, int out_size) {
    const float* C1  = (const float*)d_in[0];   // (16, 1024, 3)
    const float* C   = (const float*)d_in[1];   // (1024, 3)
    const float* dom = (const float*)d_in[2];   // (16384, 3)

    prep1_kernel<<<NSLICE + NSRC, 1024>>>(C1, C, dom);
    prep2_kernel<<<dim3(NCELLS, NSRC), 128>>>();
    theta_kernel<<<dim3(NCELLS, NSRC), 160>>>();
    reduce_kernel<<<NB, 256>>>((float*)d_out);
}

// round 10
// speedup vs baseline: 1.6535x; 1.0706x over previous
#include <cuda_runtime.h>

#define KPTS    16384
#define NATOMS  1024
#define NB      16
#define NSRC    17      // source 0 = C, sources 1..16 = C1[b]
#define NC      5       // cells per axis (h = 2.0)
#define NCELLS  125
#define NSLICE  16      // dom binning slices (1024 points each)
#define SLCAP   40      // dom points per (cell, slice) capacity (mean 8.2)
#define ACAP    40      // atoms per (source, cell) capacity (mean 8.2)
#define DCAP    640     // max dom points per cell (16*40)
#define SCAP    448     // gathered neighbor-atom capacity (mean 221)
#define NPAIR   (SCAP / 2)
#define RSLICE  16      // reduction slices (1024 points each)

// L = inv2s * log2(e) = 2*pi * 1.4426950408889634
#define LCONST  9.064720283654388f
#define INV2L   (1.0f / (2.0f * LCONST))

typedef unsigned long long u64;

// static scratch (no allocations allowed)
__device__ float4     g_binned[NSRC * NCELLS * ACAP];
__device__ int        g_acount[NSRC * NCELLS];
__device__ int        g_dslice[NCELLS * NSLICE * SLCAP];
__device__ int        g_dcnt2[NCELLS * NSLICE];
__device__ float4     g_kcoef[KPTS];
__device__ ulonglong2 g_pairsA[NSRC * NCELLS * NPAIR];  // (x0,x1),(y0,y1)
__device__ ulonglong2 g_pairsB[NSRC * NCELLS * NPAIR];  // (z0,z1),(w0,w1)
__device__ int        g_pcount[NSRC * NCELLS];          // pair counts
__device__ int        g_kidx[NCELLS * DCAP];            // stitched point ids
__device__ float4     g_kc[NCELLS * DCAP];              // stitched kcoefs
__device__ int        g_dcountc[NCELLS];
__device__ float      g_theta[NSRC * KPTS];
__device__ float      g_partial[NB * RSLICE];

__device__ __forceinline__ int cell_of(float x, float y, float z) {
    int cx = min(NC - 1, max(0, (int)(x * 0.5f)));
    int cy = min(NC - 1, max(0, (int)(y * 0.5f)));
    int cz = min(NC - 1, max(0, (int)(z * 0.5f)));
    return (cz * NC + cy) * NC + cx;
}

// ---- packed f32x2 helpers --------------------------------------------------
__device__ __forceinline__ u64 pk2(float lo, float hi) {
    u64 r; asm("mov.b64 %0, {%1, %2};" : "=l"(r) : "f"(lo), "f"(hi)); return r;
}
__device__ __forceinline__ void upk2(u64 v, float& lo, float& hi) {
    asm("mov.b64 {%0, %1}, %2;" : "=f"(lo), "=f"(hi) : "l"(v));
}
__device__ __forceinline__ u64 fma2(u64 a, u64 b, u64 c) {
    u64 r; asm("fma.rn.f32x2 %0, %1, %2, %3;" : "=l"(r) : "l"(a), "l"(b), "l"(c)); return r;
}
__device__ __forceinline__ u64 add2(u64 a, u64 b) {
    u64 r; asm("add.rn.f32x2 %0, %1, %2;" : "=l"(r) : "l"(a), "l"(b)); return r;
}
__device__ __forceinline__ float ex2(float a) {
    float e; asm("ex2.approx.ftz.f32 %0, %1;" : "=f"(e) : "f"(a)); return e;
}

// ---------------------------------------------------------------------------
// prep1: 33 blocks x 1024 threads.
// Blocks 0..15: dom binning by 1024-point slice (slot order from smem atomics
//   is FP-irrelevant: each point's theta goes to its own index and the final
//   dot is summed in fixed k order). Also writes per-point kcoef.
// Blocks 16..32: deterministic atom binning (atom index order preserved).
// ---------------------------------------------------------------------------
__global__ void __launch_bounds__(1024) prep1_kernel(const float* __restrict__ C1,
                                                     const float* __restrict__ C,
                                                     const float* __restrict__ dom) {
    const int tid = threadIdx.x;
    const int bid = blockIdx.x;

    if (bid < NSLICE) {
        __shared__ int hist[NCELLS];
        if (tid < NCELLS) hist[tid] = 0;
        const int k = bid * 1024 + tid;
        const float x = dom[k * 3 + 0];
        const float y = dom[k * 3 + 1];
        const float z = dom[k * 3 + 2];
        g_kcoef[k] = make_float4(x, y, z, -LCONST * (x * x + y * y + z * z));
        const int c = cell_of(x, y, z);
        __syncthreads();
        int slot = atomicAdd(&hist[c], 1);
        if (slot < SLCAP) g_dslice[(c * NSLICE + bid) * SLCAP + slot] = k;
        __syncthreads();
        if (tid < NCELLS) g_dcnt2[tid * NSLICE + bid] = min(hist[tid], SLCAP);
    } else {
        __shared__ int wcnt[32 * 128];           // [warp][cell]
        const int s = bid - NSLICE;
        const float* src = (s == 0) ? C : (C1 + (size_t)(s - 1) * NATOMS * 3);
        const int lane = tid & 31;
        const int w    = tid >> 5;

        #pragma unroll
        for (int i = 0; i < 4; ++i) wcnt[tid + i * 1024] = 0;

        const float x = src[tid * 3 + 0];
        const float y = src[tid * 3 + 1];
        const float z = src[tid * 3 + 2];
        const int   c = cell_of(x, y, z);
        __syncthreads();

        unsigned mm  = __match_any_sync(0xffffffffu, c);
        int     rank = __popc(mm & ((1u << lane) - 1u));
        if (rank == 0) wcnt[w * 128 + c] = __popc(mm);
        __syncthreads();

        if (tid < NCELLS) {
            int acc = 0;
            #pragma unroll
            for (int ww = 0; ww < 32; ++ww) {
                int v = wcnt[ww * 128 + tid];
                wcnt[ww * 128 + tid] = acc;       // exclusive warp base
                acc += v;
            }
            g_acount[s * NCELLS + tid] = min(acc, ACAP);
        }
        __syncthreads();

        int pos = wcnt[w * 128 + c] + rank;
        if (pos < ACAP) {
            float phi = x * x + y * y + z * z;
            g_binned[(s * NCELLS + c) * ACAP + pos] =
                make_float4(2.f * LCONST * x, 2.f * LCONST * y,
                            2.f * LCONST * z, -LCONST * phi);
        }
    }
}

// ---------------------------------------------------------------------------
// prep2: grid (125, 17) x 128 threads. Per (cell, source):
//   gather 27-cell neighbor atoms (deterministic order), prune to atoms
//   within distance 2.0 of the home cell cube (dropped terms < 2^-36 each),
//   pack into f32x2 pairs, write to global pair lists.
// Blocks with s==0 additionally stitch the cell's dom points into contiguous
//   (idx, kcoef) arrays so theta reads them with zero preamble.
// ---------------------------------------------------------------------------
__global__ void __launch_bounds__(128) prep2_kernel() {
    __shared__ float4 satoms[SCAP + 1];
    __shared__ int    ncl[27], scnt[27];
    __shared__ int    sNk;
    const int cell = blockIdx.x;
    const int s    = blockIdx.y;
    const int tid  = threadIdx.x;
    const int lane = tid & 31;
    const int cx = cell % NC, cy = (cell / NC) % NC, cz = cell / (NC * NC);

    if (tid < 27) {
        int dx = tid % 3 - 1, dy = (tid / 3) % 3 - 1, dz = tid / 9 - 1;
        int nx = cx + dx, ny = cy + dy, nz = cz + dz;
        bool ok = (unsigned)nx < NC && (unsigned)ny < NC && (unsigned)nz < NC;
        int nc2 = ok ? (nz * NC + ny) * NC + nx : -1;
        ncl[tid]  = nc2;
        scnt[tid] = ok ? g_acount[s * NCELLS + nc2] : 0;
    }
    __syncthreads();

    // gather (uniform traversal, deterministic order)
    int base = 0;
    #pragma unroll 1
    for (int ci = 0; ci < 27; ++ci) {
        int cnt = scnt[ci];
        if (cnt) {
            const float4* srcp = g_binned + (s * NCELLS + ncl[ci]) * ACAP;
            for (int i = tid; i < cnt; i += 128) {
                int pos = base + i;
                if (pos < SCAP) satoms[pos] = srcp[i];
            }
            base += cnt;
        }
    }
    const int ntot = min(base, SCAP);
    __syncthreads();

    // prune (warp 0, deterministic in-place ballot compaction)
    if (tid < 32) {
        const float lox = cx * 2.f, hix = lox + 2.f;
        const float loy = cy * 2.f, hiy = loy + 2.f;
        const float loz = cz * 2.f, hiz = loz + 2.f;
        int nk = 0;
        for (int i0 = 0; i0 < ntot; i0 += 32) {
            int i = i0 + lane;
            bool keep = false;
            float4 a;
            if (i < ntot) {
                a = satoms[i];
                float x = a.x * INV2L, y = a.y * INV2L, z = a.z * INV2L;
                float dx = fmaxf(fmaxf(lox - x, x - hix), 0.f);
                float dy = fmaxf(fmaxf(loy - y, y - hiy), 0.f);
                float dz = fmaxf(fmaxf(loz - z, z - hiz), 0.f);
                keep = fmaf(dx, dx, fmaf(dy, dy, dz * dz)) <= 4.0f;
            }
            unsigned m = __ballot_sync(0xffffffffu, keep);
            __syncwarp();
            if (keep) satoms[nk + __popc(m & ((1u << lane) - 1u))] = a;
            nk += __popc(m);
        }
        if (lane == 0) {
            if (nk & 1) satoms[nk] = make_float4(0.f, 0.f, 0.f, -1e30f);
            sNk = nk;
        }
    }
    __syncthreads();

    const int npairs = (sNk + 1) >> 1;
    ulonglong2* gA = g_pairsA + (size_t)(s * NCELLS + cell) * NPAIR;
    ulonglong2* gB = g_pairsB + (size_t)(s * NCELLS + cell) * NPAIR;
    for (int jp = tid; jp < npairs; jp += 128) {
        float4 a = satoms[2 * jp];
        float4 b = satoms[2 * jp + 1];
        gA[jp] = make_ulonglong2(pk2(a.x, b.x), pk2(a.y, b.y));
        gB[jp] = make_ulonglong2(pk2(a.z, b.z), pk2(a.w, b.w));
    }
    if (tid == 0) g_pcount[s * NCELLS + cell] = npairs;

    if (s == 0) {
        // stitch this cell's dom points into contiguous (idx, kcoef) arrays
        __shared__ int scnt16[NSLICE], soff16[NSLICE + 1];
        if (tid < NSLICE) scnt16[tid] = g_dcnt2[cell * NSLICE + tid];
        __syncthreads();
        if (tid == 0) {
            int a = 0;
            #pragma unroll
            for (int i = 0; i < NSLICE; ++i) { soff16[i] = a; a += scnt16[i]; }
            soff16[NSLICE] = a;
            g_dcountc[cell] = a;
        }
        __syncthreads();
        for (int idx = tid; idx < NSLICE * SLCAP; idx += 128) {
            int sl = idx / SLCAP, j = idx % SLCAP;
            if (j < scnt16[sl]) {
                int k = g_dslice[(cell * NSLICE + sl) * SLCAP + j];
                int pos = soff16[sl] + j;
                g_kidx[cell * DCAP + pos] = k;
                g_kc[cell * DCAP + pos]   = g_kcoef[k];
            }
        }
    }
}

// ---------------------------------------------------------------------------
// theta: grid (125, 17) x 160 threads, smem = pair buffer only (~7.2 KB).
// Preamble is a strided copy of the packed pair list + one sync; inner loop
// is the MUFU-bound f32x2 chain. Deterministic summation order.
// ---------------------------------------------------------------------------
__global__ void __launch_bounds__(160) theta_kernel() {
    __shared__ ulonglong2 sA[NPAIR];
    __shared__ ulonglong2 sB[NPAIR];
    const int cell = blockIdx.x;
    const int s    = blockIdx.y;
    const int tid  = threadIdx.x;

    const int npairs = g_pcount[s * NCELLS + cell];
    const int npts   = g_dcountc[cell];
    const ulonglong2* gA = g_pairsA + (size_t)(s * NCELLS + cell) * NPAIR;
    const ulonglong2* gB = g_pairsB + (size_t)(s * NCELLS + cell) * NPAIR;
    for (int i = tid; i < npairs; i += 160) {
        sA[i] = gA[i];
        sB[i] = gB[i];
    }
    __syncthreads();

    for (int p = tid; p < npts; p += 160) {
        const int idx = g_kidx[cell * DCAP + p];
        const float4 kc = g_kc[cell * DCAP + p];
        const u64 kx2 = pk2(kc.x, kc.x);
        const u64 ky2 = pk2(kc.y, kc.y);
        const u64 kz2 = pk2(kc.z, kc.z);
        const u64 kw2 = pk2(kc.w, kc.w);
        u64 acc = 0ull;
        #pragma unroll 4
        for (int jp = 0; jp < npairs; ++jp) {
            ulonglong2 A = sA[jp];
            ulonglong2 B = sB[jp];
            u64 t = add2(B.y, kw2);
            t = fma2(kz2, B.x, t);
            t = fma2(ky2, A.y, t);
            t = fma2(kx2, A.x, t);
            float lo, hi; upk2(t, lo, hi);
            acc = add2(acc, pk2(ex2(lo), ex2(hi)));
        }
        float a0, a1; upk2(acc, a0, a1);
        g_theta[s * KPTS + idx] = a0 + a1;
    }
}

// ---------------------------------------------------------------------------
// Reduction stage A: grid (NB, RSLICE) x 256 threads. Block (b, j) dots the
// 1024-point slice j of theta[b+1] . theta[0] into g_partial[b*RSLICE+j].
// Fixed tree order -> deterministic.
// ---------------------------------------------------------------------------
__global__ void __launch_bounds__(256) reduceA_kernel() {
    __shared__ float red[8];
    const int b = blockIdx.x, j = blockIdx.y;
    const int tid = threadIdx.x, lane = tid & 31, w = tid >> 5;
    const float* tb = g_theta + (size_t)(1 + b) * KPTS + j * 1024;
    const float* t0 = g_theta + j * 1024;

    float p = 0.f;
    #pragma unroll
    for (int i = 0; i < 4; ++i) {
        int k = i * 256 + tid;
        p += tb[k] * t0[k];
    }
    #pragma unroll
    for (int st = 16; st > 0; st >>= 1)
        p += __shfl_down_sync(0xffffffffu, p, st);
    if (lane == 0) red[w] = p;
    __syncthreads();
    if (tid == 0) {
        float a = 0.f;
        #pragma unroll
        for (int i = 0; i < 8; ++i) a += red[i];
        g_partial[b * RSLICE + j] = a;
    }
}

// ---------------------------------------------------------------------------
// Reduction stage B: 1 block x 256 threads. Thread group of 16 folds the 16
// partials of one b. out[b] = 1 - clip(scale * dot, 0, 1),
// scale = A*V/sqrt(n1*n2) = 8 * (1000/16384) / 1024.
// ---------------------------------------------------------------------------
__global__ void __launch_bounds__(256) reduceB_kernel(float* __restrict__ out) {
    __shared__ float sp[NB][RSLICE];
    const int tid = threadIdx.x;
    const int b = tid >> 4, j = tid & 15;
    sp[b][j] = g_partial[b * RSLICE + j];
    __syncthreads();
    #pragma unroll
    for (int st = 8; st > 0; st >>= 1) {
        if (j < st) sp[b][j] += sp[b][j + st];
        __syncthreads();
    }
    if (j == 0) {
        float dot = 4.76837158203125e-4f * sp[b][0];
        dot = fminf(fmaxf(dot, 0.f), 1.f);
        out[b] = 1.f - dot;
    }
}

extern "C" void kernel_launch(void* const* d_in, const int* in_sizes, int n_in,
                              void* d_out, int out_size) {
    const float* C1  = (const float*)d_in[0];   // (16, 1024, 3)
    const float* C   = (const float*)d_in[1];   // (1024, 3)
    const float* dom = (const float*)d_in[2];   // (16384, 3)

    prep1_kernel<<<NSLICE + NSRC, 1024>>>(C1, C, dom);
    prep2_kernel<<<dim3(NCELLS, NSRC), 128>>>();
    theta_kernel<<<dim3(NCELLS, NSRC), 160>>>();
    reduceA_kernel<<<dim3(NB, RSLICE), 256>>>();
    reduceB_kernel<<<1, 256>>>((float*)d_out);
}